// round 6
// baseline (speedup 1.0000x reference)
#include <cuda_runtime.h>

#define Dd   30
#define DP   32    // padded hidden
#define H1d  15
#define H1P  16
#define Tt   512
#define BPW  4     // batch elements per warp
#define STRIDE 36  // padded state row stride (floats): conflict-free & 16B-aligned

__device__ __forceinline__ float fast_tanh(float x) {
    // accurate to ~1e-6; clamp avoids inf/inf
    x = fminf(15.f, fmaxf(-15.f, x));
    float e = __expf(2.f * x);
    return __fdividef(e - 1.f, e + 1.f);
}

// pre[j0..j0+3] = bsum + WiT^T·in + WhT^T·h   (30-dim padded to 32, weights transposed [d][j])
__device__ __forceinline__ float4 rnn_pre(const float* __restrict__ inbuf,
                                          const float* __restrict__ hbuf,
                                          const float* __restrict__ WiT,
                                          const float* __restrict__ WhT,
                                          const float* __restrict__ bsum, int j0)
{
    float4 b = *(const float4*)(bsum + j0);
    float a0 = b.x, a1 = b.y, a2 = b.z, a3 = b.w;
#pragma unroll
    for (int g = 0; g < 8; g++) {
        float4 xv = *(const float4*)(inbuf + 4 * g);
        float4 hv = *(const float4*)(hbuf + 4 * g);
        const float* xp = (const float*)&xv;
        const float* hp = (const float*)&hv;
#pragma unroll
        for (int k = 0; k < 4; k++) {
            float4 wx = *(const float4*)(WiT + (4 * g + k) * DP + j0);
            float4 wh = *(const float4*)(WhT + (4 * g + k) * DP + j0);
            a0 += xp[k] * wx.x; a0 += hp[k] * wh.x;
            a1 += xp[k] * wx.y; a1 += hp[k] * wh.y;
            a2 += xp[k] * wx.z; a2 += hp[k] * wh.z;
            a3 += xp[k] * wx.w; a3 += hp[k] * wh.w;
        }
    }
    return make_float4(a0, a1, a2, a3);
}

__global__ void __launch_bounds__(32, 8)
rnn_fused_kernel(const float* __restrict__ x,
                 const float* __restrict__ Wih1, const float* __restrict__ Whh1,
                 const float* __restrict__ bih1, const float* __restrict__ bhh1,
                 const float* __restrict__ Wih2, const float* __restrict__ Whh2,
                 const float* __restrict__ bih2, const float* __restrict__ bhh2,
                 const float* __restrict__ W1,  const float* __restrict__ b1,
                 const float* __restrict__ W2,  const float* __restrict__ b2,
                 const float* __restrict__ W3,  const float* __restrict__ b3,
                 float* __restrict__ out)
{
    __shared__ __align__(16) float wih1T[DP * DP], whh1T[DP * DP];
    __shared__ __align__(16) float wih2T[DP * DP], whh2T[DP * DP];
    __shared__ __align__(16) float w1T[DP * H1P], w2T[H1P * H1P], w3s[H1P];
    __shared__ __align__(16) float bs1[DP], bs2[DP], b1s[H1P], b2s[H1P];
    __shared__ __align__(16) float xs[BPW * STRIDE], h1s[BPW * STRIDE], h2s[BPW * STRIDE];
    __shared__ __align__(16) float z1s[BPW * STRIDE], z2s[BPW * STRIDE];
    __shared__ __align__(16) float ys[BPW * 33];

    const int lane = threadIdx.x;

    // ---- zero-fill (padding must be 0) ----
    for (int i = lane; i < DP * DP; i += 32) { wih1T[i] = 0.f; whh1T[i] = 0.f; wih2T[i] = 0.f; whh2T[i] = 0.f; }
    for (int i = lane; i < DP * H1P; i += 32) w1T[i] = 0.f;
    for (int i = lane; i < H1P * H1P; i += 32) w2T[i] = 0.f;
    if (lane < H1P) { w3s[lane] = 0.f; b1s[lane] = 0.f; b2s[lane] = 0.f; }
    if (lane < DP)  { bs1[lane] = 0.f; bs2[lane] = 0.f; }
    for (int i = lane; i < BPW * STRIDE; i += 32) { xs[i] = 0.f; h1s[i] = 0.f; h2s[i] = 0.f; z1s[i] = 0.f; z2s[i] = 0.f; }
    __syncwarp();

    // ---- load + transpose weights into smem ----
    for (int i = lane; i < Dd * Dd; i += 32) {
        int j = i / Dd, d = i % Dd;
        wih1T[d * DP + j] = Wih1[i]; whh1T[d * DP + j] = Whh1[i];
        wih2T[d * DP + j] = Wih2[i]; whh2T[d * DP + j] = Whh2[i];
    }
    for (int i = lane; i < H1d * Dd; i += 32) { int j = i / Dd, d = i % Dd; w1T[d * H1P + j] = W1[i]; }
    for (int i = lane; i < H1d * H1d; i += 32) { int j = i / H1d, d = i % H1d; w2T[d * H1P + j] = W2[i]; }
    if (lane < H1d) { w3s[lane] = W3[lane]; b1s[lane] = b1[lane]; b2s[lane] = b2[lane]; }
    if (lane < Dd)  { bs1[lane] = bih1[lane] + bhh1[lane]; bs2[lane] = bih2[lane] + bhh2[lane]; }
    const float b3v = b3[0];
    __syncwarp();

    const int bl = lane >> 3;      // 0..3: batch element within warp
    const int jg = lane & 7;       // 0..7: row group
    const int j0 = jg * 4;         // 4 rows per lane for RNN layers
    const int j0m = jg * 2;        // 2 rows per lane for MLP layers
    const int b0 = blockIdx.x * BPW;

    // x loader assignment: 60 float2 per step (4 b × 15 pairs); lane handles i=lane and i=lane+32
    const int i1 = lane, i2 = lane + 32;
    const int bb1i = i1 / 15, d21 = i1 % 15;
    const int bb2i = i2 / 15, d22 = i2 % 15;
    const bool p2 = (i2 < 60);
    const float2* xp1 = ((const float2*)x) + ((size_t)(b0 + bb1i) * Tt * Dd) / 2 + d21;
    const float2* xp2 = p2 ? (((const float2*)x) + ((size_t)(b0 + bb2i) * Tt * Dd) / 2 + d22) : xp1;
    const int xdst1 = bb1i * STRIDE + d21 * 2;
    const int xdst2 = p2 ? (bb2i * STRIDE + d22 * 2) : xdst1;

    float* __restrict__ myx  = xs  + bl * STRIDE;
    float* __restrict__ myh1 = h1s + bl * STRIDE;
    float* __restrict__ myh2 = h2s + bl * STRIDE;
    float* __restrict__ myz1 = z1s + bl * STRIDE;
    float* __restrict__ myz2 = z2s + bl * STRIDE;

    for (int t = 0; t < Tt; t++) {
        // ---- stage x_t ----
        float2 v1 = xp1[(size_t)t * (Dd / 2)];
        *(float2*)(xs + xdst1) = v1;
        if (p2) *(float2*)(xs + xdst2) = xp2[(size_t)t * (Dd / 2)];
        __syncwarp();

        // ---- RNN layer 1 ----
        float4 p = rnn_pre(myx, myh1, wih1T, whh1T, bs1, j0);
        float4 hn = make_float4(fast_tanh(p.x), fast_tanh(p.y), fast_tanh(p.z), fast_tanh(p.w));
        __syncwarp();                      // all lanes done reading old h1
        *(float4*)(h1s + bl * STRIDE + j0) = hn;
        __syncwarp();

        // ---- RNN layer 2 (input = new h1) ----
        p = rnn_pre(myh1, myh2, wih2T, whh2T, bs2, j0);
        hn = make_float4(fast_tanh(p.x), fast_tanh(p.y), fast_tanh(p.z), fast_tanh(p.w));
        __syncwarp();                      // all lanes done reading old h2
        *(float4*)(h2s + bl * STRIDE + j0) = hn;
        __syncwarp();

        // ---- MLP z1 = tanh(W1 h2 + b1): 2 rows per lane (16 rows, row 15 is zero pad) ----
        {
            float c0 = b1s[j0m], c1 = b1s[j0m + 1];
#pragma unroll
            for (int g = 0; g < 8; g++) {
                float4 iv = *(const float4*)(myh2 + 4 * g);
                const float* ip = (const float*)&iv;
#pragma unroll
                for (int k = 0; k < 4; k++) {
                    float2 w = *(const float2*)(w1T + (4 * g + k) * H1P + j0m);
                    c0 += ip[k] * w.x;
                    c1 += ip[k] * w.y;
                }
            }
            __syncwarp();                  // prev-step readers of z1 done long ago; cheap ordering
            *(float2*)(myz1 + j0m) = make_float2(fast_tanh(c0), fast_tanh(c1));
            __syncwarp();
        }

        // ---- MLP z2 = tanh(W2 z1 + b2) ----
        {
            float c0 = b2s[j0m], c1 = b2s[j0m + 1];
#pragma unroll
            for (int g = 0; g < 4; g++) {
                float4 iv = *(const float4*)(myz1 + 4 * g);
                const float* ip = (const float*)&iv;
#pragma unroll
                for (int k = 0; k < 4; k++) {
                    float2 w = *(const float2*)(w2T + (4 * g + k) * H1P + j0m);
                    c0 += ip[k] * w.x;
                    c1 += ip[k] * w.y;
                }
            }
            *(float2*)(myz2 + j0m) = make_float2(fast_tanh(c0), fast_tanh(c1));
            __syncwarp();
        }

        // ---- y = W3 z2 + b3 (lane jg==0 of each batch group) ----
        if (jg == 0) {
            float y = b3v;
#pragma unroll
            for (int k = 0; k < H1P; k++) y += w3s[k] * myz2[k];
            ys[bl * 33 + (t & 31)] = y;
        }

        // ---- coalesced flush every 32 steps ----
        if ((t & 31) == 31) {
            __syncwarp();
            int tb = t - 31;
#pragma unroll
            for (int bb = 0; bb < BPW; bb++)
                out[(size_t)(b0 + bb) * Tt + tb + lane] = ys[bb * 33 + lane];
        }
    }
}

extern "C" void kernel_launch(void* const* d_in, const int* in_sizes, int n_in,
                              void* d_out, int out_size)
{
    const float* x    = (const float*)d_in[0];
    const float* Wih1 = (const float*)d_in[1];
    const float* Whh1 = (const float*)d_in[2];
    const float* bih1 = (const float*)d_in[3];
    const float* bhh1 = (const float*)d_in[4];
    const float* Wih2 = (const float*)d_in[5];
    const float* Whh2 = (const float*)d_in[6];
    const float* bih2 = (const float*)d_in[7];
    const float* bhh2 = (const float*)d_in[8];
    const float* W1   = (const float*)d_in[9];
    const float* b1   = (const float*)d_in[10];
    const float* W2   = (const float*)d_in[11];
    const float* b2   = (const float*)d_in[12];
    const float* W3   = (const float*)d_in[13];
    const float* b3   = (const float*)d_in[14];

    int B = in_sizes[0] / (Tt * Dd);   // 4096
    dim3 grid(B / BPW), block(32);
    rnn_fused_kernel<<<grid, block>>>(x, Wih1, Whh1, bih1, bhh1,
                                      Wih2, Whh2, bih2, bhh2,
                                      W1, b1, W2, b2, W3, b3,
                                      (float*)d_out);
}